// round 1
// baseline (speedup 1.0000x reference)
#include <cuda_runtime.h>
#include <math.h>

// ---------------- problem constants ----------------
constexpr int Nn_   = 8192;        // nodes
constexpr int S_    = 24;          // timesteps
constexpr int C_    = 4;           // input channels
constexpr int E_    = 65536;       // edges
constexpr int WIN_  = 20;
constexpr int NW_   = S_ - WIN_;   // 4 windows
constexpr int Y_    = 128;         // final GCN channels
constexpr int FLAT_ = WIN_ * Y_;   // 2560
constexpr int PROJ_ = 1280;
constexpr int HID_  = 128;
constexpr int G4_   = 4 * HID_;    // 512
constexpr int LBL_  = 12;
constexpr int NS_   = Nn_ * S_;    // 196608 rows
constexpr int ROWS_ = Nn_ * NW_;   // 32768 pooled rows
constexpr int KBIG_ = FLAT_;       // 2560 (GEMM K)

// ---------------- device scratch (static, no allocation) ----------------
__device__ float d_deg [Nn_];
__device__ float d_dinv[Nn_];
__device__ float d_norm[E_];
__device__ float d_agg [NS_ * 64];                 // max Fi = 64  (50.3 MB)
__device__ float d_x0  [NS_ * 128];                // 100.7 MB
__device__ float d_x1  [NS_ * 128];                // 100.7 MB
__device__ float d_pooled[(size_t)ROWS_ * FLAT_];  // 335.5 MB
__device__ float d_M   [G4_ * KBIG_];              // fused w_ih @ proj_w (512x2560)
__device__ float d_b0  [G4_];
__device__ float d_gatex[(size_t)ROWS_ * G4_];     // 67 MB
__device__ float d_h   [Nn_ * HID_];
__device__ float d_c   [Nn_ * HID_];
__device__ float d_whhT[HID_ * G4_];

// ---------------- math helpers ----------------
__device__ __forceinline__ float tanh_acc(float x) {
    // accurate even under fast-math: 1 - 2/(exp(2x)+1); handles +-inf correctly
    float e2 = __expf(2.0f * x);
    return 1.0f - 2.0f / (e2 + 1.0f);
}
__device__ __forceinline__ float sigmoid_acc(float x) {
    return 1.0f / (1.0f + __expf(-x));
}

// ---------------- degree / norm ----------------
__global__ void zero_deg_k() {
    int i = blockIdx.x * 256 + threadIdx.x;
    if (i < Nn_) d_deg[i] = 0.0f;
}
__global__ void deg_acc_k(const int* __restrict__ ei, const float* __restrict__ ea) {
    int e = blockIdx.x * 256 + threadIdx.x;
    if (e < E_) atomicAdd(&d_deg[ei[E_ + e]], ea[e]);
}
__global__ void dinv_k() {
    int i = blockIdx.x * 256 + threadIdx.x;
    if (i < Nn_) d_dinv[i] = rsqrtf(d_deg[i] + 1.0f);  // self-loop weight 1 included
}
__global__ void norm_k(const int* __restrict__ ei, const float* __restrict__ ea) {
    int e = blockIdx.x * 256 + threadIdx.x;
    if (e < E_) d_norm[e] = d_dinv[ei[e]] * ea[e] * d_dinv[ei[E_ + e]];
}

// ---------------- GCN aggregation (on INPUT feature dim) ----------------
template<int L>
__global__ void self_k(const float* __restrict__ X) {
    constexpr int SFi = S_ * (4 << L);
    int idx = blockIdx.x * 256 + threadIdx.x;
    if (idx >= Nn_ * SFi) return;
    int n = idx / SFi;
    float dv = d_dinv[n];
    d_agg[idx] = dv * dv * X[idx];
}
template<int L>
__global__ void edge_k(const float* __restrict__ X, const int* __restrict__ ei) {
    constexpr int SFi = S_ * (4 << L);
    int e = blockIdx.x;
    int j = blockIdx.y * 256 + threadIdx.x;
    if (j >= SFi) return;
    int s = __ldg(&ei[e]);
    int d = __ldg(&ei[E_ + e]);
    float nr = __ldg(&d_norm[e]);
    atomicAdd(&d_agg[d * SFi + j], nr * __ldg(&X[s * SFi + j]));
}
// out = tanh(agg @ W^T + b), W is (Fo, Fi) row-major
template<int L>
__global__ __launch_bounds__(256) void transform_k(const float* __restrict__ W,
                                                   const float* __restrict__ b,
                                                   float* __restrict__ out) {
    constexpr int Fi = 4 << L;
    constexpr int Fo = 8 << L;
    constexpr int R  = 256 / Fo;   // rows per block; R*Fi == 128 always
    __shared__ float sWt[Fi * Fo];
    __shared__ float sB[Fo];
    __shared__ float sRow[R * Fi];
    int tid = threadIdx.x;
    for (int i = tid; i < Fi * Fo; i += 256) {
        int o = i / Fi, c = i - o * Fi;
        sWt[c * Fo + o] = W[i];
    }
    if (tid < Fo) sB[tid] = b[tid];
    size_t row0 = (size_t)blockIdx.x * R;
    for (int i = tid; i < R * Fi; i += 256) sRow[i] = d_agg[row0 * Fi + i];
    __syncthreads();
    int rl = tid / Fo;
    int o  = tid - rl * Fo;
    float acc = sB[o];
#pragma unroll
    for (int c = 0; c < Fi; c++) acc += sRow[rl * Fi + c] * sWt[c * Fo + o];
    out[row0 * Fo + tid] = tanh_acc(acc);
}

// ---------------- fused window + conv1d(K=5,SAME) + pair max-pool ----------------
__global__ __launch_bounds__(256) void conv_pool_k(const float* __restrict__ cw,
                                                   const float* __restrict__ cb) {
    int row = blockIdx.x;            // n*4 + w
    int n = row >> 2, w = row & 3;
    const float* flat = d_x0 + ((size_t)n * S_ + w) * Y_;   // contiguous 2560
    __shared__ float sf[FLAT_ + 8];
    int tid = threadIdx.x;
    for (int i = tid; i < FLAT_; i += 256) sf[4 + i] = flat[i];
    if (tid < 4) { sf[tid] = 0.0f; sf[4 + FLAT_ + tid] = 0.0f; }
    float c0 = __ldg(&cb[0]), c1 = __ldg(&cb[1]);
    float w0[5], w1[5];
#pragma unroll
    for (int k = 0; k < 5; k++) { w0[k] = __ldg(&cw[k]); w1[k] = __ldg(&cw[5 + k]); }
    __syncthreads();
    float* po = d_pooled + (size_t)row * FLAT_;
    for (int j = tid; j < FLAT_; j += 256) {
        int f = (j >= 1280);
        int q = j - f * 1280;
        const float* base = &sf[2 * q + 2];
        float t0 = base[0], t1 = base[1], t2 = base[2],
              t3 = base[3], t4 = base[4], t5 = base[5];
        float v0, v1;
        if (!f) {
            v0 = c0 + w0[0]*t0 + w0[1]*t1 + w0[2]*t2 + w0[3]*t3 + w0[4]*t4;
            v1 = c0 + w0[0]*t1 + w0[1]*t2 + w0[2]*t3 + w0[3]*t4 + w0[4]*t5;
        } else {
            v0 = c1 + w1[0]*t0 + w1[1]*t1 + w1[2]*t2 + w1[3]*t3 + w1[4]*t4;
            v1 = c1 + w1[0]*t1 + w1[1]*t2 + w1[2]*t3 + w1[3]*t4 + w1[4]*t5;
        }
        po[j] = fmaxf(v0, v1);
    }
}

// ---------------- generic double-buffered SGEMM 128x128x8, 8x8/thread -------
// C(M,N) = A(M,K) * op(B) [+ bias per column]
// TRANSB=true : B is (N,K) row-major (compute A*B^T)
// TRANSB=false: B is (K,N) row-major
template<bool TRANSB, bool BIAS>
__global__ __launch_bounds__(256) void sgemm_k(const float* __restrict__ A,
                                               const float* __restrict__ B,
                                               const float* __restrict__ bias,
                                               float* __restrict__ C,
                                               int Mdim, int Ndim, int Kdim) {
    __shared__ float As[2][8][128];
    __shared__ float Bs[2][8][128];
    const int tid = threadIdx.x;
    const int m0 = blockIdx.x * 128;
    const int n0 = blockIdx.y * 128;
    const int tx = tid & 15;
    const int ty = tid >> 4;

    const int arow = tid >> 1;
    const int acol = (tid & 1) * 4;
    const float* Ap = A + (size_t)(m0 + arow) * Kdim + acol;

    int brow, bcol;
    const float* Bp;
    if (TRANSB) { brow = tid >> 1; bcol = (tid & 1) * 4;
                  Bp = B + (size_t)(n0 + brow) * Kdim + bcol; }
    else        { brow = tid >> 5; bcol = (tid & 31) * 4;
                  Bp = B + (size_t)brow * Ndim + n0 + bcol; }

    float4 pa = *(const float4*)Ap;
    float4 pb = *(const float4*)Bp;

    As[0][acol + 0][arow] = pa.x;
    As[0][acol + 1][arow] = pa.y;
    As[0][acol + 2][arow] = pa.z;
    As[0][acol + 3][arow] = pa.w;
    if (TRANSB) {
        Bs[0][bcol + 0][brow] = pb.x;
        Bs[0][bcol + 1][brow] = pb.y;
        Bs[0][bcol + 2][brow] = pb.z;
        Bs[0][bcol + 3][brow] = pb.w;
    } else {
        *(float4*)&Bs[0][brow][bcol] = pb;
    }
    __syncthreads();

    float acc[8][8];
#pragma unroll
    for (int i = 0; i < 8; i++)
#pragma unroll
        for (int j = 0; j < 8; j++) acc[i][j] = 0.0f;

    const int nt = Kdim >> 3;
    for (int kt = 0; kt < nt; kt++) {
        const int cur = kt & 1;
        if (kt + 1 < nt) {
            pa = *(const float4*)(Ap + (kt + 1) * 8);
            pb = TRANSB ? *(const float4*)(Bp + (kt + 1) * 8)
                        : *(const float4*)(Bp + (size_t)(kt + 1) * 8 * Ndim);
        }
#pragma unroll
        for (int kk = 0; kk < 8; kk++) {
            float4 a0 = *(const float4*)&As[cur][kk][ty * 8];
            float4 a1 = *(const float4*)&As[cur][kk][ty * 8 + 4];
            float4 b0 = *(const float4*)&Bs[cur][kk][tx * 8];
            float4 b1 = *(const float4*)&Bs[cur][kk][tx * 8 + 4];
            float ra[8] = {a0.x, a0.y, a0.z, a0.w, a1.x, a1.y, a1.z, a1.w};
            float rb[8] = {b0.x, b0.y, b0.z, b0.w, b1.x, b1.y, b1.z, b1.w};
#pragma unroll
            for (int i = 0; i < 8; i++)
#pragma unroll
                for (int j = 0; j < 8; j++) acc[i][j] += ra[i] * rb[j];
        }
        if (kt + 1 < nt) {
            const int nb = cur ^ 1;
            As[nb][acol + 0][arow] = pa.x;
            As[nb][acol + 1][arow] = pa.y;
            As[nb][acol + 2][arow] = pa.z;
            As[nb][acol + 3][arow] = pa.w;
            if (TRANSB) {
                Bs[nb][bcol + 0][brow] = pb.x;
                Bs[nb][bcol + 1][brow] = pb.y;
                Bs[nb][bcol + 2][brow] = pb.z;
                Bs[nb][bcol + 3][brow] = pb.w;
            } else {
                *(float4*)&Bs[nb][brow][bcol] = pb;
            }
        }
        __syncthreads();
    }

    float bv[8];
    if (BIAS) {
#pragma unroll
        for (int j = 0; j < 8; j++) bv[j] = __ldg(&bias[n0 + tx * 8 + j]);
    }
#pragma unroll
    for (int i = 0; i < 8; i++) {
        float* cp = C + (size_t)(m0 + ty * 8 + i) * Ndim + n0 + tx * 8;
        float4 o0, o1;
        o0.x = acc[i][0] + (BIAS ? bv[0] : 0.0f);
        o0.y = acc[i][1] + (BIAS ? bv[1] : 0.0f);
        o0.z = acc[i][2] + (BIAS ? bv[2] : 0.0f);
        o0.w = acc[i][3] + (BIAS ? bv[3] : 0.0f);
        o1.x = acc[i][4] + (BIAS ? bv[4] : 0.0f);
        o1.y = acc[i][5] + (BIAS ? bv[5] : 0.0f);
        o1.z = acc[i][6] + (BIAS ? bv[6] : 0.0f);
        o1.w = acc[i][7] + (BIAS ? bv[7] : 0.0f);
        *(float4*)cp = o0;
        *(float4*)(cp + 4) = o1;
    }
}

// ---------------- fused LSTM bias: b0 = w_ih @ proj_b + b_ih + b_hh ----------
__global__ void bias0_k(const float* __restrict__ w_ih, const float* __restrict__ proj_b,
                        const float* __restrict__ b_ih, const float* __restrict__ b_hh) {
    int g = blockIdx.x * 8 + (threadIdx.x >> 5);
    int lane = threadIdx.x & 31;
    if (g >= G4_) return;
    float p = 0.0f;
    for (int j = lane; j < PROJ_; j += 32) p += w_ih[g * PROJ_ + j] * proj_b[j];
#pragma unroll
    for (int off = 16; off; off >>= 1) p += __shfl_down_sync(0xffffffff, p, off);
    if (lane == 0) d_b0[g] = p + b_ih[g] + b_hh[g];
}

__global__ void transpose_whh_k(const float* __restrict__ whh) {
    int i = blockIdx.x * 256 + threadIdx.x;
    if (i < G4_ * HID_) {
        int k = i >> 7, j = i & 127;
        d_whhT[j * G4_ + k] = whh[i];
    }
}
__global__ void zero_hc_k() {
    int i = blockIdx.x * 256 + threadIdx.x;
    if (i < Nn_ * HID_) { d_h[i] = 0.0f; d_c[i] = 0.0f; }
}

// ---------------- LSTM step: 16 nodes / block, 512 threads (one per gate) ----
__global__ __launch_bounds__(512) void lstm_step_k(int t) {
    constexpr int BN = 16;
    int n0 = blockIdx.x * BN;
    int k = threadIdx.x;  // 0..511 gate index
    __shared__ float shT[HID_][BN];      // h transposed
    __shared__ float sg[BN][G4_];        // gate pre-activations
    for (int i = k; i < BN * HID_; i += 512) {
        int nl = i >> 7, j = i & 127;
        shT[j][nl] = d_h[(n0 + nl) * HID_ + j];
    }
    __syncthreads();
    float acc[BN];
#pragma unroll
    for (int nl = 0; nl < BN; nl++)
        acc[nl] = d_gatex[((size_t)(n0 + nl) * NW_ + t) * G4_ + k];
#pragma unroll 4
    for (int j = 0; j < HID_; j++) {
        float wv = d_whhT[j * G4_ + k];
        const float4* hp = (const float4*)&shT[j][0];
#pragma unroll
        for (int q = 0; q < 4; q++) {
            float4 hv = hp[q];
            acc[4 * q + 0] += hv.x * wv;
            acc[4 * q + 1] += hv.y * wv;
            acc[4 * q + 2] += hv.z * wv;
            acc[4 * q + 3] += hv.w * wv;
        }
    }
#pragma unroll
    for (int nl = 0; nl < BN; nl++) sg[nl][k] = acc[nl];
    __syncthreads();
    for (int i = k; i < BN * HID_; i += 512) {
        int nl = i >> 7, u = i & 127;
        float gi = sg[nl][u];
        float gf = sg[nl][128 + u];
        float gg = sg[nl][256 + u];
        float go = sg[nl][384 + u];
        int gidx = (n0 + nl) * HID_ + u;
        float cc = d_c[gidx];
        float cn = sigmoid_acc(gf) * cc + sigmoid_acc(gi) * tanh_acc(gg);
        d_c[gidx] = cn;
        d_h[gidx] = sigmoid_acc(go) * tanh_acc(cn);
    }
}

// ---------------- output projection ----------------
__global__ void out_k(const float* __restrict__ ow, const float* __restrict__ ob,
                      float* __restrict__ out) {
    int n = blockIdx.x;
    int lane = threadIdx.x;  // 32
    float hv[4];
#pragma unroll
    for (int i = 0; i < 4; i++) hv[i] = d_h[n * HID_ + lane + 32 * i];
    for (int l = 0; l < LBL_; l++) {
        float p = 0.0f;
#pragma unroll
        for (int i = 0; i < 4; i++) p += hv[i] * __ldg(&ow[l * HID_ + lane + 32 * i]);
#pragma unroll
        for (int off = 16; off; off >>= 1) p += __shfl_down_sync(0xffffffff, p, off);
        if (lane == 0) out[n * LBL_ + l] = p + ob[l];
    }
}

// ---------------- launch ----------------
extern "C" void kernel_launch(void* const* d_in, const int* in_sizes, int n_in,
                              void* d_out, int out_size) {
    const float* inputs = (const float*)d_in[0];
    const int*   ei     = (const int*)d_in[1];
    const float* ea     = (const float*)d_in[2];
    const float* W[5]  = {(const float*)d_in[3], (const float*)d_in[5], (const float*)d_in[7],
                          (const float*)d_in[9], (const float*)d_in[11]};
    const float* bb[5] = {(const float*)d_in[4], (const float*)d_in[6], (const float*)d_in[8],
                          (const float*)d_in[10], (const float*)d_in[12]};
    const float* conv_w = (const float*)d_in[13];
    const float* conv_b = (const float*)d_in[14];
    const float* proj_w = (const float*)d_in[15];
    const float* proj_b = (const float*)d_in[16];
    const float* w_ih   = (const float*)d_in[17];
    const float* w_hh   = (const float*)d_in[18];
    const float* b_ih   = (const float*)d_in[19];
    const float* b_hh   = (const float*)d_in[20];
    const float* out_w  = (const float*)d_in[21];
    const float* out_b  = (const float*)d_in[22];
    float* out = (float*)d_out;

    float *pX0, *pX1, *pM, *pB0, *pPooled, *pGx;
    cudaGetSymbolAddress((void**)&pX0, d_x0);
    cudaGetSymbolAddress((void**)&pX1, d_x1);
    cudaGetSymbolAddress((void**)&pM,  d_M);
    cudaGetSymbolAddress((void**)&pB0, d_b0);
    cudaGetSymbolAddress((void**)&pPooled, d_pooled);
    cudaGetSymbolAddress((void**)&pGx, d_gatex);

    // --- degrees / norms ---
    zero_deg_k<<<(Nn_ + 255) / 256, 256>>>();
    deg_acc_k<<<E_ / 256, 256>>>(ei, ea);
    dinv_k<<<(Nn_ + 255) / 256, 256>>>();
    norm_k<<<E_ / 256, 256>>>(ei, ea);

    // --- 5 GCN layers (aggregate-then-transform) ---
    // layer 0: in = inputs, out = x0
    {
        constexpr int SFi = S_ * 4;
        self_k<0><<<(Nn_ * SFi + 255) / 256, 256>>>(inputs);
        edge_k<0><<<dim3(E_, (SFi + 255) / 256), 256>>>(inputs, ei);
        transform_k<0><<<NS_ * 8 / 256, 256>>>(W[0], bb[0], pX0);
    }
    {   // layer 1: x0 -> x1
        constexpr int SFi = S_ * 8;
        self_k<1><<<(Nn_ * SFi + 255) / 256, 256>>>(pX0);
        edge_k<1><<<dim3(E_, (SFi + 255) / 256), 256>>>(pX0, ei);
        transform_k<1><<<NS_ * 16 / 256, 256>>>(W[1], bb[1], pX1);
    }
    {   // layer 2: x1 -> x0
        constexpr int SFi = S_ * 16;
        self_k<2><<<(Nn_ * SFi + 255) / 256, 256>>>(pX1);
        edge_k<2><<<dim3(E_, (SFi + 255) / 256), 256>>>(pX1, ei);
        transform_k<2><<<NS_ * 32 / 256, 256>>>(W[2], bb[2], pX0);
    }
    {   // layer 3: x0 -> x1
        constexpr int SFi = S_ * 32;
        self_k<3><<<(Nn_ * SFi + 255) / 256, 256>>>(pX0);
        edge_k<3><<<dim3(E_, (SFi + 255) / 256), 256>>>(pX0, ei);
        transform_k<3><<<NS_ * 64 / 256, 256>>>(W[3], bb[3], pX1);
    }
    {   // layer 4: x1 -> x0  (final features live in x0)
        constexpr int SFi = S_ * 64;
        self_k<4><<<(Nn_ * SFi + 255) / 256, 256>>>(pX1);
        edge_k<4><<<dim3(E_, (SFi + 255) / 256), 256>>>(pX1, ei);
        transform_k<4><<<NS_ * 128 / 256, 256>>>(W[4], bb[4], pX0);
    }

    // --- fused window + conv + pool ---
    conv_pool_k<<<ROWS_, 256>>>(conv_w, conv_b);

    // --- fused projection matrix M = w_ih @ proj_w  (512 x 2560) ---
    sgemm_k<false, false><<<dim3(G4_ / 128, KBIG_ / 128), 256>>>(
        w_ih, proj_w, nullptr, pM, G4_, KBIG_, PROJ_);
    bias0_k<<<G4_ / 8, 256>>>(w_ih, proj_b, b_ih, b_hh);

    // --- main GEMM: gate_x = pooled @ M^T + b0   (32768 x 512, K=2560) ---
    sgemm_k<true, true><<<dim3(ROWS_ / 128, G4_ / 128), 256>>>(
        pPooled, pM, pB0, pGx, ROWS_, G4_, KBIG_);

    // --- LSTM ---
    transpose_whh_k<<<(G4_ * HID_ + 255) / 256, 256>>>(w_hh);
    zero_hc_k<<<(Nn_ * HID_ + 255) / 256, 256>>>();
    for (int t = 0; t < NW_; t++) lstm_step_k<<<Nn_ / 16, 512>>>(t);

    // --- output ---
    out_k<<<Nn_, 32>>>(out_w, out_b, out);
}

// round 2
// speedup vs baseline: 1.0007x; 1.0007x over previous
#include <cuda_runtime.h>
#include <math.h>

// ---------------- problem constants ----------------
constexpr int Nn_   = 8192;        // nodes
constexpr int S_    = 24;          // timesteps
constexpr int C_    = 4;           // input channels
constexpr int E_    = 65536;       // edges
constexpr int WIN_  = 20;
constexpr int NW_   = S_ - WIN_;   // 4 windows
constexpr int Y_    = 128;         // final GCN channels
constexpr int FLAT_ = WIN_ * Y_;   // 2560
constexpr int PROJ_ = 1280;
constexpr int HID_  = 128;
constexpr int G4_   = 4 * HID_;    // 512
constexpr int LBL_  = 12;
constexpr int NS_   = Nn_ * S_;    // 196608 rows
constexpr int ROWS_ = Nn_ * NW_;   // 32768 pooled rows
constexpr int KBIG_ = FLAT_;       // 2560 (GEMM K)

// ---------------- device scratch (static, no allocation) ----------------
__device__ float d_deg [Nn_];
__device__ float d_dinv[Nn_];
__device__ float d_norm[E_];
__device__ float d_agg [NS_ * 64];                 // max Fi = 64  (50.3 MB)
__device__ float d_x0  [NS_ * 128];                // 100.7 MB
__device__ float d_x1  [NS_ * 128];                // 100.7 MB
__device__ float d_pooled[(size_t)ROWS_ * FLAT_];  // 335.5 MB
__device__ float d_M   [G4_ * KBIG_];              // fused w_ih @ proj_w (512x2560)
__device__ float d_b0  [G4_];
__device__ float d_gatex[(size_t)ROWS_ * G4_];     // 67 MB
__device__ float d_h   [Nn_ * HID_];
__device__ float d_c   [Nn_ * HID_];
__device__ float d_whhT[HID_ * G4_];

// ---------------- math helpers ----------------
__device__ __forceinline__ float tanh_acc(float x) {
    // accurate even under fast-math: 1 - 2/(exp(2x)+1); handles +-inf correctly
    float e2 = __expf(2.0f * x);
    return 1.0f - 2.0f / (e2 + 1.0f);
}
__device__ __forceinline__ float sigmoid_acc(float x) {
    return 1.0f / (1.0f + __expf(-x));
}

// ---------------- degree / norm ----------------
__global__ void zero_deg_k() {
    int i = blockIdx.x * 256 + threadIdx.x;
    if (i < Nn_) d_deg[i] = 0.0f;
}
__global__ void deg_acc_k(const int* __restrict__ ei, const float* __restrict__ ea) {
    int e = blockIdx.x * 256 + threadIdx.x;
    if (e < E_) atomicAdd(&d_deg[ei[E_ + e]], ea[e]);
}
__global__ void dinv_k() {
    int i = blockIdx.x * 256 + threadIdx.x;
    if (i < Nn_) d_dinv[i] = rsqrtf(d_deg[i] + 1.0f);  // self-loop weight 1 included
}
__global__ void norm_k(const int* __restrict__ ei, const float* __restrict__ ea) {
    int e = blockIdx.x * 256 + threadIdx.x;
    if (e < E_) d_norm[e] = d_dinv[ei[e]] * ea[e] * d_dinv[ei[E_ + e]];
}

// ---------------- GCN aggregation (on INPUT feature dim) ----------------
template<int L>
__global__ void self_k(const float* __restrict__ X) {
    constexpr int SFi = S_ * (4 << L);
    int idx = blockIdx.x * 256 + threadIdx.x;
    if (idx >= Nn_ * SFi) return;
    int n = idx / SFi;
    float dv = d_dinv[n];
    d_agg[idx] = dv * dv * X[idx];
}
template<int L>
__global__ void edge_k(const float* __restrict__ X, const int* __restrict__ ei) {
    constexpr int SFi = S_ * (4 << L);
    int e = blockIdx.x;
    int j = blockIdx.y * 256 + threadIdx.x;
    if (j >= SFi) return;
    int s = __ldg(&ei[e]);
    int d = __ldg(&ei[E_ + e]);
    float nr = __ldg(&d_norm[e]);
    atomicAdd(&d_agg[d * SFi + j], nr * __ldg(&X[s * SFi + j]));
}
// out = tanh(agg @ W^T + b), W is (Fo, Fi) row-major
template<int L>
__global__ __launch_bounds__(256) void transform_k(const float* __restrict__ W,
                                                   const float* __restrict__ b,
                                                   float* __restrict__ out) {
    constexpr int Fi = 4 << L;
    constexpr int Fo = 8 << L;
    constexpr int R  = 256 / Fo;   // rows per block; R*Fi == 128 always
    __shared__ float sWt[Fi * Fo];
    __shared__ float sB[Fo];
    __shared__ float sRow[R * Fi];
    int tid = threadIdx.x;
    for (int i = tid; i < Fi * Fo; i += 256) {
        int o = i / Fi, c = i - o * Fi;
        sWt[c * Fo + o] = W[i];
    }
    if (tid < Fo) sB[tid] = b[tid];
    size_t row0 = (size_t)blockIdx.x * R;
    for (int i = tid; i < R * Fi; i += 256) sRow[i] = d_agg[row0 * Fi + i];
    __syncthreads();
    int rl = tid / Fo;
    int o  = tid - rl * Fo;
    float acc = sB[o];
#pragma unroll
    for (int c = 0; c < Fi; c++) acc += sRow[rl * Fi + c] * sWt[c * Fo + o];
    out[row0 * Fo + tid] = tanh_acc(acc);
}

// ---------------- fused window + conv1d(K=5,SAME) + pair max-pool ----------------
__global__ __launch_bounds__(256) void conv_pool_k(const float* __restrict__ cw,
                                                   const float* __restrict__ cb) {
    int row = blockIdx.x;            // n*4 + w
    int n = row >> 2, w = row & 3;
    const float* flat = d_x0 + ((size_t)n * S_ + w) * Y_;   // contiguous 2560
    __shared__ float sf[FLAT_ + 8];
    int tid = threadIdx.x;
    for (int i = tid; i < FLAT_; i += 256) sf[4 + i] = flat[i];
    if (tid < 4) { sf[tid] = 0.0f; sf[4 + FLAT_ + tid] = 0.0f; }
    float c0 = __ldg(&cb[0]), c1 = __ldg(&cb[1]);
    float w0[5], w1[5];
#pragma unroll
    for (int k = 0; k < 5; k++) { w0[k] = __ldg(&cw[k]); w1[k] = __ldg(&cw[5 + k]); }
    __syncthreads();
    float* po = d_pooled + (size_t)row * FLAT_;
    for (int j = tid; j < FLAT_; j += 256) {
        int f = (j >= 1280);
        int q = j - f * 1280;
        const float* base = &sf[2 * q + 2];
        float t0 = base[0], t1 = base[1], t2 = base[2],
              t3 = base[3], t4 = base[4], t5 = base[5];
        float v0, v1;
        if (!f) {
            v0 = c0 + w0[0]*t0 + w0[1]*t1 + w0[2]*t2 + w0[3]*t3 + w0[4]*t4;
            v1 = c0 + w0[0]*t1 + w0[1]*t2 + w0[2]*t3 + w0[3]*t4 + w0[4]*t5;
        } else {
            v0 = c1 + w1[0]*t0 + w1[1]*t1 + w1[2]*t2 + w1[3]*t3 + w1[4]*t4;
            v1 = c1 + w1[0]*t1 + w1[1]*t2 + w1[2]*t3 + w1[3]*t4 + w1[4]*t5;
        }
        po[j] = fmaxf(v0, v1);
    }
}

// ---------------- generic double-buffered SGEMM 128x128x8, 8x8/thread -------
// C(M,N) = A(M,K) * op(B) [+ bias per column]
// TRANSB=true : B is (N,K) row-major (compute A*B^T)
// TRANSB=false: B is (K,N) row-major
template<bool TRANSB, bool BIAS>
__global__ __launch_bounds__(256) void sgemm_k(const float* __restrict__ A,
                                               const float* __restrict__ B,
                                               const float* __restrict__ bias,
                                               float* __restrict__ C,
                                               int Mdim, int Ndim, int Kdim) {
    __shared__ float As[2][8][128];
    __shared__ float Bs[2][8][128];
    const int tid = threadIdx.x;
    const int m0 = blockIdx.x * 128;
    const int n0 = blockIdx.y * 128;
    const int tx = tid & 15;
    const int ty = tid >> 4;

    const int arow = tid >> 1;
    const int acol = (tid & 1) * 4;
    const float* Ap = A + (size_t)(m0 + arow) * Kdim + acol;

    int brow, bcol;
    const float* Bp;
    if (TRANSB) { brow = tid >> 1; bcol = (tid & 1) * 4;
                  Bp = B + (size_t)(n0 + brow) * Kdim + bcol; }
    else        { brow = tid >> 5; bcol = (tid & 31) * 4;
                  Bp = B + (size_t)brow * Ndim + n0 + bcol; }

    float4 pa = *(const float4*)Ap;
    float4 pb = *(const float4*)Bp;

    As[0][acol + 0][arow] = pa.x;
    As[0][acol + 1][arow] = pa.y;
    As[0][acol + 2][arow] = pa.z;
    As[0][acol + 3][arow] = pa.w;
    if (TRANSB) {
        Bs[0][bcol + 0][brow] = pb.x;
        Bs[0][bcol + 1][brow] = pb.y;
        Bs[0][bcol + 2][brow] = pb.z;
        Bs[0][bcol + 3][brow] = pb.w;
    } else {
        *(float4*)&Bs[0][brow][bcol] = pb;
    }
    __syncthreads();

    float acc[8][8];
#pragma unroll
    for (int i = 0; i < 8; i++)
#pragma unroll
        for (int j = 0; j < 8; j++) acc[i][j] = 0.0f;

    const int nt = Kdim >> 3;
    for (int kt = 0; kt < nt; kt++) {
        const int cur = kt & 1;
        if (kt + 1 < nt) {
            pa = *(const float4*)(Ap + (kt + 1) * 8);
            pb = TRANSB ? *(const float4*)(Bp + (kt + 1) * 8)
                        : *(const float4*)(Bp + (size_t)(kt + 1) * 8 * Ndim);
        }
#pragma unroll
        for (int kk = 0; kk < 8; kk++) {
            float4 a0 = *(const float4*)&As[cur][kk][ty * 8];
            float4 a1 = *(const float4*)&As[cur][kk][ty * 8 + 4];
            float4 b0 = *(const float4*)&Bs[cur][kk][tx * 8];
            float4 b1 = *(const float4*)&Bs[cur][kk][tx * 8 + 4];
            float ra[8] = {a0.x, a0.y, a0.z, a0.w, a1.x, a1.y, a1.z, a1.w};
            float rb[8] = {b0.x, b0.y, b0.z, b0.w, b1.x, b1.y, b1.z, b1.w};
#pragma unroll
            for (int i = 0; i < 8; i++)
#pragma unroll
                for (int j = 0; j < 8; j++) acc[i][j] += ra[i] * rb[j];
        }
        if (kt + 1 < nt) {
            const int nb = cur ^ 1;
            As[nb][acol + 0][arow] = pa.x;
            As[nb][acol + 1][arow] = pa.y;
            As[nb][acol + 2][arow] = pa.z;
            As[nb][acol + 3][arow] = pa.w;
            if (TRANSB) {
                Bs[nb][bcol + 0][brow] = pb.x;
                Bs[nb][bcol + 1][brow] = pb.y;
                Bs[nb][bcol + 2][brow] = pb.z;
                Bs[nb][bcol + 3][brow] = pb.w;
            } else {
                *(float4*)&Bs[nb][brow][bcol] = pb;
            }
        }
        __syncthreads();
    }

    float bv[8];
    if (BIAS) {
#pragma unroll
        for (int j = 0; j < 8; j++) bv[j] = __ldg(&bias[n0 + tx * 8 + j]);
    }
#pragma unroll
    for (int i = 0; i < 8; i++) {
        float* cp = C + (size_t)(m0 + ty * 8 + i) * Ndim + n0 + tx * 8;
        float4 o0, o1;
        o0.x = acc[i][0] + (BIAS ? bv[0] : 0.0f);
        o0.y = acc[i][1] + (BIAS ? bv[1] : 0.0f);
        o0.z = acc[i][2] + (BIAS ? bv[2] : 0.0f);
        o0.w = acc[i][3] + (BIAS ? bv[3] : 0.0f);
        o1.x = acc[i][4] + (BIAS ? bv[4] : 0.0f);
        o1.y = acc[i][5] + (BIAS ? bv[5] : 0.0f);
        o1.z = acc[i][6] + (BIAS ? bv[6] : 0.0f);
        o1.w = acc[i][7] + (BIAS ? bv[7] : 0.0f);
        *(float4*)cp = o0;
        *(float4*)(cp + 4) = o1;
    }
}

// ---------------- fused LSTM bias: b0 = w_ih @ proj_b + b_ih + b_hh ----------
__global__ void bias0_k(const float* __restrict__ w_ih, const float* __restrict__ proj_b,
                        const float* __restrict__ b_ih, const float* __restrict__ b_hh) {
    int g = blockIdx.x * 8 + (threadIdx.x >> 5);
    int lane = threadIdx.x & 31;
    if (g >= G4_) return;
    float p = 0.0f;
    for (int j = lane; j < PROJ_; j += 32) p += w_ih[g * PROJ_ + j] * proj_b[j];
#pragma unroll
    for (int off = 16; off; off >>= 1) p += __shfl_down_sync(0xffffffff, p, off);
    if (lane == 0) d_b0[g] = p + b_ih[g] + b_hh[g];
}

__global__ void transpose_whh_k(const float* __restrict__ whh) {
    int i = blockIdx.x * 256 + threadIdx.x;
    if (i < G4_ * HID_) {
        int k = i >> 7, j = i & 127;
        d_whhT[j * G4_ + k] = whh[i];
    }
}
__global__ void zero_hc_k() {
    int i = blockIdx.x * 256 + threadIdx.x;
    if (i < Nn_ * HID_) { d_h[i] = 0.0f; d_c[i] = 0.0f; }
}

// ---------------- LSTM step: 16 nodes / block, 512 threads (one per gate) ----
__global__ __launch_bounds__(512) void lstm_step_k(int t) {
    constexpr int BN = 16;
    int n0 = blockIdx.x * BN;
    int k = threadIdx.x;  // 0..511 gate index
    __shared__ float shT[HID_][BN];      // h transposed
    __shared__ float sg[BN][G4_];        // gate pre-activations
    for (int i = k; i < BN * HID_; i += 512) {
        int nl = i >> 7, j = i & 127;
        shT[j][nl] = d_h[(n0 + nl) * HID_ + j];
    }
    __syncthreads();
    float acc[BN];
#pragma unroll
    for (int nl = 0; nl < BN; nl++)
        acc[nl] = d_gatex[((size_t)(n0 + nl) * NW_ + t) * G4_ + k];
#pragma unroll 4
    for (int j = 0; j < HID_; j++) {
        float wv = d_whhT[j * G4_ + k];
        const float4* hp = (const float4*)&shT[j][0];
#pragma unroll
        for (int q = 0; q < 4; q++) {
            float4 hv = hp[q];
            acc[4 * q + 0] += hv.x * wv;
            acc[4 * q + 1] += hv.y * wv;
            acc[4 * q + 2] += hv.z * wv;
            acc[4 * q + 3] += hv.w * wv;
        }
    }
#pragma unroll
    for (int nl = 0; nl < BN; nl++) sg[nl][k] = acc[nl];
    __syncthreads();
    for (int i = k; i < BN * HID_; i += 512) {
        int nl = i >> 7, u = i & 127;
        float gi = sg[nl][u];
        float gf = sg[nl][128 + u];
        float gg = sg[nl][256 + u];
        float go = sg[nl][384 + u];
        int gidx = (n0 + nl) * HID_ + u;
        float cc = d_c[gidx];
        float cn = sigmoid_acc(gf) * cc + sigmoid_acc(gi) * tanh_acc(gg);
        d_c[gidx] = cn;
        d_h[gidx] = sigmoid_acc(go) * tanh_acc(cn);
    }
}

// ---------------- output projection ----------------
__global__ void out_k(const float* __restrict__ ow, const float* __restrict__ ob,
                      float* __restrict__ out) {
    int n = blockIdx.x;
    int lane = threadIdx.x;  // 32
    float hv[4];
#pragma unroll
    for (int i = 0; i < 4; i++) hv[i] = d_h[n * HID_ + lane + 32 * i];
    for (int l = 0; l < LBL_; l++) {
        float p = 0.0f;
#pragma unroll
        for (int i = 0; i < 4; i++) p += hv[i] * __ldg(&ow[l * HID_ + lane + 32 * i]);
#pragma unroll
        for (int off = 16; off; off >>= 1) p += __shfl_down_sync(0xffffffff, p, off);
        if (lane == 0) out[n * LBL_ + l] = p + ob[l];
    }
}

// ---------------- launch ----------------
extern "C" void kernel_launch(void* const* d_in, const int* in_sizes, int n_in,
                              void* d_out, int out_size) {
    const float* inputs = (const float*)d_in[0];
    const int*   ei     = (const int*)d_in[1];
    const float* ea     = (const float*)d_in[2];
    const float* W[5]  = {(const float*)d_in[3], (const float*)d_in[5], (const float*)d_in[7],
                          (const float*)d_in[9], (const float*)d_in[11]};
    const float* bb[5] = {(const float*)d_in[4], (const float*)d_in[6], (const float*)d_in[8],
                          (const float*)d_in[10], (const float*)d_in[12]};
    const float* conv_w = (const float*)d_in[13];
    const float* conv_b = (const float*)d_in[14];
    const float* proj_w = (const float*)d_in[15];
    const float* proj_b = (const float*)d_in[16];
    const float* w_ih   = (const float*)d_in[17];
    const float* w_hh   = (const float*)d_in[18];
    const float* b_ih   = (const float*)d_in[19];
    const float* b_hh   = (const float*)d_in[20];
    const float* out_w  = (const float*)d_in[21];
    const float* out_b  = (const float*)d_in[22];
    float* out = (float*)d_out;

    float *pX0, *pX1, *pM, *pB0, *pPooled, *pGx;
    cudaGetSymbolAddress((void**)&pX0, d_x0);
    cudaGetSymbolAddress((void**)&pX1, d_x1);
    cudaGetSymbolAddress((void**)&pM,  d_M);
    cudaGetSymbolAddress((void**)&pB0, d_b0);
    cudaGetSymbolAddress((void**)&pPooled, d_pooled);
    cudaGetSymbolAddress((void**)&pGx, d_gatex);

    // --- degrees / norms ---
    zero_deg_k<<<(Nn_ + 255) / 256, 256>>>();
    deg_acc_k<<<E_ / 256, 256>>>(ei, ea);
    dinv_k<<<(Nn_ + 255) / 256, 256>>>();
    norm_k<<<E_ / 256, 256>>>(ei, ea);

    // --- 5 GCN layers (aggregate-then-transform) ---
    // layer 0: in = inputs, out = x0
    {
        constexpr int SFi = S_ * 4;
        self_k<0><<<(Nn_ * SFi + 255) / 256, 256>>>(inputs);
        edge_k<0><<<dim3(E_, (SFi + 255) / 256), 256>>>(inputs, ei);
        transform_k<0><<<NS_ * 8 / 256, 256>>>(W[0], bb[0], pX0);
    }
    {   // layer 1: x0 -> x1
        constexpr int SFi = S_ * 8;
        self_k<1><<<(Nn_ * SFi + 255) / 256, 256>>>(pX0);
        edge_k<1><<<dim3(E_, (SFi + 255) / 256), 256>>>(pX0, ei);
        transform_k<1><<<NS_ * 16 / 256, 256>>>(W[1], bb[1], pX1);
    }
    {   // layer 2: x1 -> x0
        constexpr int SFi = S_ * 16;
        self_k<2><<<(Nn_ * SFi + 255) / 256, 256>>>(pX1);
        edge_k<2><<<dim3(E_, (SFi + 255) / 256), 256>>>(pX1, ei);
        transform_k<2><<<NS_ * 32 / 256, 256>>>(W[2], bb[2], pX0);
    }
    {   // layer 3: x0 -> x1
        constexpr int SFi = S_ * 32;
        self_k<3><<<(Nn_ * SFi + 255) / 256, 256>>>(pX0);
        edge_k<3><<<dim3(E_, (SFi + 255) / 256), 256>>>(pX0, ei);
        transform_k<3><<<NS_ * 64 / 256, 256>>>(W[3], bb[3], pX1);
    }
    {   // layer 4: x1 -> x0  (final features live in x0)
        constexpr int SFi = S_ * 64;
        self_k<4><<<(Nn_ * SFi + 255) / 256, 256>>>(pX1);
        edge_k<4><<<dim3(E_, (SFi + 255) / 256), 256>>>(pX1, ei);
        transform_k<4><<<NS_ * 128 / 256, 256>>>(W[4], bb[4], pX0);
    }

    // --- fused window + conv + pool ---
    conv_pool_k<<<ROWS_, 256>>>(conv_w, conv_b);

    // --- fused projection matrix M = w_ih @ proj_w  (512 x 2560) ---
    sgemm_k<false, false><<<dim3(G4_ / 128, KBIG_ / 128), 256>>>(
        w_ih, proj_w, nullptr, pM, G4_, KBIG_, PROJ_);
    bias0_k<<<G4_ / 8, 256>>>(w_ih, proj_b, b_ih, b_hh);

    // --- main GEMM: gate_x = pooled @ M^T + b0   (32768 x 512, K=2560) ---
    sgemm_k<true, true><<<dim3(ROWS_ / 128, G4_ / 128), 256>>>(
        pPooled, pM, pB0, pGx, ROWS_, G4_, KBIG_);

    // --- LSTM ---
    transpose_whh_k<<<(G4_ * HID_ + 255) / 256, 256>>>(w_hh);
    zero_hc_k<<<(Nn_ * HID_ + 255) / 256, 256>>>();
    for (int t = 0; t < NW_; t++) lstm_step_k<<<Nn_ / 16, 512>>>(t);

    // --- output ---
    out_k<<<Nn_, 32>>>(out_w, out_b, out);
}